// round 5
// baseline (speedup 1.0000x reference)
#include <cuda_runtime.h>
#include <math.h>

// ---------------------------------------------------------------------------
// LFQ forward, B=4, DIM=512, T=2048, codebook_dim=14, NB_CODE=16384
// d_out layout (float32): out[4*512*2048] | indices[4*2048] | aux_loss[1]
// 3 launches: K1 in+mid+halfprod, K2 outproj||avg-GEMM, K3 cred+final
// ---------------------------------------------------------------------------

#define DIM_ 512
#define T_   2048
#define N_   8192
#define C_   14
#define J_   16384
#define OUT_IDX  4194304
#define OUT_LOSS 4202496
#define ABLK 148           // avg-GEMM blocks (one per SM)

// Static scratch (no allocations allowed)
__device__ int      g_idx[N_];
__device__ float    g_Lo[N_ * 128];        // low  7-bit half products (jl, c=13..7)
__device__ float    g_Hi[N_ * 128];        // high 7-bit half products (jh, c=6..0)
__device__ float    g_Ap[256];             // 128 blocks x {commit, entropy}
__device__ float    g_Bp[ABLK * J_];       // partial avg_prob sums
__device__ float    g_Cp[64];              // codebook-entropy partials
__device__ unsigned g_cnt;                 // last-block counter (reset by K1)

// ---------------------------------------------------------------------------
// K1: in-projection + quantize/losses + half-product production.
// grid = 128 blocks x 256 threads; block owns 64 samples.
// Thread (s = t&63, chunk = t>>6) does a 128-d partial dot for its sample.
// ---------------------------------------------------------------------------
__global__ void __launch_bounds__(256) k_in_mid(const float* __restrict__ x,
                                                const float* __restrict__ Win,
                                                const float* __restrict__ bin,
                                                float* __restrict__ dout) {
    // Phase-A smem: ws[512][16]  (32KB).  Phase-B reuses the same buffer.
    __shared__ __align__(16) float sbuf[512 * 16];
    float (*ws)[16] = (float(*)[16])sbuf;

    int t = threadIdx.x;
    if (blockIdx.x == 0 && t == 0) g_cnt = 0;   // reset K3's counter each call

    // Load Win [14][512] transposed into ws[d][c] (c>=14 zeroed)
    for (int i = t; i < C_ * DIM_; i += 256) {
        int c = i >> 9, d = i & 511;
        ws[d][c] = Win[i];
    }
    for (int i = t; i < DIM_; i += 256) { ws[i][14] = 0.f; ws[i][15] = 0.f; }
    __syncthreads();

    int s     = t & 63;
    int chunk = t >> 6;
    int n0    = blockIdx.x * 64;
    int n     = n0 + s;
    int b     = n >> 11, tt = n & 2047;
    const float* xp = x + ((size_t)(b * DIM_ + chunk * 128)) * T_ + tt;

    float acc[C_];
#pragma unroll
    for (int c = 0; c < C_; c++) acc[c] = 0.f;

#pragma unroll 4
    for (int dd = 0; dd < 128; dd++) {
        float xv = xp[(size_t)dd * T_];                              // coalesced
        const float4* w4 = reinterpret_cast<const float4*>(ws[chunk * 128 + dd]); // broadcast
        float4 w0 = w4[0], w1 = w4[1], w2 = w4[2], w3 = w4[3];
        acc[0]  += xv * w0.x; acc[1]  += xv * w0.y; acc[2]  += xv * w0.z; acc[3]  += xv * w0.w;
        acc[4]  += xv * w1.x; acc[5]  += xv * w1.y; acc[6]  += xv * w1.z; acc[7]  += xv * w1.w;
        acc[8]  += xv * w2.x; acc[9]  += xv * w2.y; acc[10] += xv * w2.z; acc[11] += xv * w2.w;
        acc[12] += xv * w3.x; acc[13] += xv * w3.y;
    }

    // Phase B: repartition sbuf (all ws reads complete after this barrier)
    __syncthreads();
    float (*hbuf)[64][17] = (float(*)[64][17])sbuf;                  // 4352 floats
    float (*pbuf)[17]     = (float(*)[17])(sbuf + 4352);             // 1088 floats
    float *red            = sbuf + 4352 + 1088;                      // 128 floats

#pragma unroll
    for (int c = 0; c < C_; c++) hbuf[chunk][s][c] = acc[c];
    __syncthreads();

    // mid: 64 threads, one sample each
    if (t < 64) {
        int   idx = 0;
        float commit = 0.f, ent = 0.f;
#pragma unroll
        for (int c = 0; c < C_; c++) {
            float hv = bin[c] + hbuf[0][t][c] + hbuf[1][t][c] + hbuf[2][t][c] + hbuf[3][t][c];
            bool pos = hv > 0.f;
            float q  = pos ? 1.f : -1.f;
            if (pos) idx |= (1 << (13 - c));
            float d = hv - q;
            commit += d * d;
            // p(bit=1) = sigmoid(400 h), computed via z=exp(-400|h|)
            float z   = __expf(-400.f * fabsf(hv));
            float pb  = 1.f / (1.f + z);
            float psm = z * pb;
            float e = -pb * __logf(pb);
            if (psm > 0.f) e -= psm * __logf(psm);
            ent += e;
            pbuf[t][c] = pos ? pb : psm;
        }
        g_idx[n0 + t] = idx;
        dout[OUT_IDX + n0 + t] = (float)idx;
        red[t]      = commit;
        red[64 + t] = ent;
    }
    __syncthreads();
    // reduce commit/ent over 64 samples (threads 0..31)
    if (t < 32) {
        float cm = red[t] + red[t + 32];
        float en = red[64 + t] + red[96 + t];
#pragma unroll
        for (int o = 16; o > 0; o >>= 1) {
            cm += __shfl_down_sync(0xffffffffu, cm, o);
            en += __shfl_down_sync(0xffffffffu, en, o);
        }
        if (t == 0) { g_Ap[blockIdx.x * 2] = cm; g_Ap[blockIdx.x * 2 + 1] = en; }
    }

    // production: warp w handles samples w*8..w*8+7; lane covers jl=lane+q*32.
    // Lo: j bit k (k<7) <-> c = 13-k.  Hi: jh bit k <-> c = 6-k.
    {
        int warp = t >> 5, lane = t & 31;
#pragma unroll
        for (int si = 0; si < 8; si++) {
            int ss = warp * 8 + si;
            float lowL = 1.f, lowH = 1.f;
#pragma unroll
            for (int k = 0; k < 5; k++) {
                float pL = pbuf[ss][13 - k];                         // broadcast
                float pH = pbuf[ss][6 - k];
                bool bit = (lane >> k) & 1;
                lowL *= bit ? pL : (1.f - pL);
                lowH *= bit ? pH : (1.f - pH);
            }
            float p5L = pbuf[ss][8], p6L = pbuf[ss][7];              // jl bits 5,6
            float p5H = pbuf[ss][1], p6H = pbuf[ss][0];              // jh bits 5,6
            float qL[4] = { (1.f - p5L) * (1.f - p6L), p5L * (1.f - p6L),
                            (1.f - p5L) * p6L,         p5L * p6L };
            float qH[4] = { (1.f - p5H) * (1.f - p6H), p5H * (1.f - p6H),
                            (1.f - p5H) * p6H,         p5H * p6H };
            float* lp = g_Lo + (size_t)(n0 + ss) * 128 + lane;
            float* hp = g_Hi + (size_t)(n0 + ss) * 128 + lane;
#pragma unroll
            for (int q = 0; q < 4; q++) {                            // coalesced 128B
                lp[q * 32] = lowL * qL[q];
                hp[q * 32] = lowH * qH[q];
            }
        }
    }
}

// ---------------------------------------------------------------------------
// K2: blocks 0..147 = avg-GEMM (pure streaming FMA), blocks 148..211 = outproj
// grid = 212 blocks x 512 threads, 2 blocks/SM
// ---------------------------------------------------------------------------
__global__ void __launch_bounds__(512, 2) k_out_avg(const float* __restrict__ Wout,
                                                    const float* __restrict__ bout,
                                                    float* __restrict__ out) {
    __shared__ float ws2[128][16];
    __shared__ float bo[128];
    int t = threadIdx.x;

    if (blockIdx.x < ABLK) {
        // ---- avg outer product: acc[jh 8][jl 4] per thread ----
        int bb = blockIdx.x;
        int ns = (bb * N_) / ABLK;
        int ne = ((bb + 1) * N_) / ABLK;
        int jl0 = (t & 31) * 4;
        int jh0 = (t >> 5) * 8;

        const float* lo = g_Lo + (size_t)ns * 128 + jl0;
        const float* hi = g_Hi + (size_t)ns * 128 + jh0;
        float4 a[8];
#pragma unroll
        for (int k = 0; k < 8; k++) a[k] = make_float4(0.f, 0.f, 0.f, 0.f);

#pragma unroll 2
        for (int nn = ns; nn < ne; ++nn, lo += 128, hi += 128) {
            float4 l  = *reinterpret_cast<const float4*>(lo);        // coalesced
            float4 h0 = *reinterpret_cast<const float4*>(hi);        // uniform/broadcast
            float4 h1 = *reinterpret_cast<const float4*>(hi + 4);
            float hv[8] = {h0.x, h0.y, h0.z, h0.w, h1.x, h1.y, h1.z, h1.w};
#pragma unroll
            for (int k = 0; k < 8; k++) {
                a[k].x += hv[k] * l.x;
                a[k].y += hv[k] * l.y;
                a[k].z += hv[k] * l.z;
                a[k].w += hv[k] * l.w;
            }
        }
        float* bp = g_Bp + (size_t)bb * J_;
#pragma unroll
        for (int k = 0; k < 8; k++)
            *reinterpret_cast<float4*>(&bp[(jh0 + k) * 128 + jl0]) = a[k];
    } else {
        // ---- out-projection: 64 blocks, thread = sample, 128 d-rows ----
        int ob    = blockIdx.x - ABLK;
        int chunk = ob & 3;
        int tile  = ob >> 2;
        int d0    = chunk * 128;
        for (int i = t; i < 128 * 16; i += 512) {
            int dd = i >> 4, c = i & 15;
            ws2[dd][c] = (c < C_) ? Wout[(d0 + dd) * C_ + c] : 0.f;
        }
        for (int i = t; i < 128; i += 512) bo[i] = bout[d0 + i];
        __syncthreads();

        int n = tile * 512 + t;
        int b = n >> 11, tt = n & 2047;
        int idx = g_idx[n];
        float sv[C_];
#pragma unroll
        for (int c = 0; c < C_; c++) sv[c] = ((idx >> (13 - c)) & 1) ? 1.f : -1.f;

        float* op = out + ((size_t)(b * DIM_ + d0)) * T_ + tt;
#pragma unroll 2
        for (int dd = 0; dd < 128; dd++) {
            const float4* w4 = reinterpret_cast<const float4*>(ws2[dd]);
            float4 w0 = w4[0], w1 = w4[1], w2 = w4[2], w3 = w4[3];
            float r = bo[dd];
            r += w0.x * sv[0]  + w0.y * sv[1]  + w0.z * sv[2]  + w0.w * sv[3];
            r += w1.x * sv[4]  + w1.y * sv[5]  + w1.z * sv[6]  + w1.w * sv[7];
            r += w2.x * sv[8]  + w2.y * sv[9]  + w2.z * sv[10] + w2.w * sv[11];
            r += w3.x * sv[12] + w3.y * sv[13];
            op[(size_t)dd * T_] = r;                                 // coalesced
        }
    }
}

// ---------------------------------------------------------------------------
// K3: reduce g_Bp -> avg_prob -> codebook-entropy partials; last block combines
// grid = 64 blocks x 256 threads
// ---------------------------------------------------------------------------
__global__ void __launch_bounds__(256) k_cred_final(float* __restrict__ dout) {
    int t = threadIdx.x;
    int e = blockIdx.x * 256 + t;
    float sum = 0.f;
#pragma unroll 4
    for (int p = 0; p < ABLK; p++) sum += g_Bp[(size_t)p * J_ + e];
    float avg  = sum * (1.f / 8192.f);
    float entc = -avg * __logf(fmaxf(avg, 1e-20f));

    __shared__ float sr[256];
    __shared__ unsigned islast;
    sr[t] = entc;
    __syncthreads();
    for (int s = 128; s > 0; s >>= 1) {
        if (t < s) sr[t] += sr[t + s];
        __syncthreads();
    }
    if (t == 0) {
        g_Cp[blockIdx.x] = sr[0];
        __threadfence();
        islast = (atomicAdd(&g_cnt, 1u) == 63u) ? 1u : 0u;
    }
    __syncthreads();

    if (islast && t < 32) {
        volatile float* cp = g_Cp;
        volatile float* ap = g_Ap;
        float cb = cp[t] + cp[t + 32];
        float cm = 0.f, en = 0.f;
#pragma unroll
        for (int i = 0; i < 4; i++) {
            cm += ap[2 * (t + 32 * i)];
            en += ap[2 * (t + 32 * i) + 1];
        }
#pragma unroll
        for (int o = 16; o > 0; o >>= 1) {
            cb += __shfl_down_sync(0xffffffffu, cb, o);
            cm += __shfl_down_sync(0xffffffffu, cm, o);
            en += __shfl_down_sync(0xffffffffu, en, o);
        }
        if (t == 0) {
            float ps_mean     = en / 8192.f;
            float commit_mean = cm / (8192.f * 14.f);
            dout[OUT_LOSS] = 0.1f * (ps_mean - cb) + commit_mean;
        }
    }
}

// ---------------------------------------------------------------------------
extern "C" void kernel_launch(void* const* d_in, const int* in_sizes, int n_in,
                              void* d_out, int out_size) {
    const float* x    = (const float*)d_in[0];
    const float* Win  = (const float*)d_in[1];
    const float* bin  = (const float*)d_in[2];
    const float* Wout = (const float*)d_in[3];
    const float* bout = (const float*)d_in[4];
    float* out = (float*)d_out;

    k_in_mid<<<128, 256>>>(x, Win, bin, out);
    k_out_avg<<<ABLK + 64, 512>>>(Wout, bout, out);
    k_cred_final<<<64, 256>>>(out);
}